// round 5
// baseline (speedup 1.0000x reference)
#include <cuda_runtime.h>
#include <cuda_bf16.h>

// CosFace margin transform.
// Inputs:  d_in[0] = logits  [B, C]  float32  (B=512, C=100000)
//          d_in[1] = labels  [B]     int32 OR int64 (detected in-kernel)
// Output:  d_out = concat( diff_logits[B, C-1], sin_theta[B], sin_theta_plus_m[B], sin_m[B] ) float32
//
// diff_logits[b, j] = 64 * (logits[b, col(j)] - (logits[b, label[b]] - 0.35))
//   where col(j) = j + (j >= label[b])   (drop the label column)
// sin_theta        = sin(acos(t))
// sin_theta_plus_m = sin(acos(t - 0.35))
// sin_m            = sin(acos(t-0.35) - acos(t))
//
// Pure streaming workload: ~205 MB read + ~205 MB write. HBM-bound.

static constexpr float SCALE_S  = 64.0f;
static constexpr float MARGIN_M = 0.35f;
static constexpr int   CHUNK    = 4096;   // columns per block
static constexpr int   TPB      = 256;    // threads per block

__global__ __launch_bounds__(TPB)
void cosface_kernel(const float* __restrict__ logits,
                    const int* __restrict__ labels32,  // raw label words
                    float* __restrict__ out,
                    int B, int C)
{
    // ---- In-block label-dtype detection (reads only B int32 words = the
    // guaranteed-safe minimum buffer size for either dtype). If labels are
    // int64 with values < C, every odd 32-bit word is 0. If int32, the odd
    // words are real labels; P(all 256 are 0) ~ (1e-5)^256 ~ 0.
    __shared__ int s_nz;
    if (threadIdx.x == 0) s_nz = 0;
    __syncthreads();
    {
        int acc = 0;
        for (int i = threadIdx.x; i < B / 2; i += TPB)
            acc |= labels32[2 * i + 1];
        if (acc != 0) atomicOr(&s_nz, 1);
    }
    __syncthreads();
    const bool labels_are_i64 = (s_nz == 0);

    const int b = blockIdx.y;
    int lab = labels_are_i64 ? labels32[2 * b]     // low word of int64
                             : labels32[b];        // plain int32
    // Hang-proof clamp: wrong detection fails with rel_err, never OOB.
    lab = min(max(lab, 0), C - 1);

    const float* __restrict__ row = logits + (size_t)b * (size_t)C;
    const float t  = __ldg(row + lab);            // target logit (broadcast, L2-hit)
    const float ft = t - MARGIN_M;                // final target logit

    float* __restrict__ orow = out + (size_t)b * (size_t)(C - 1);

    // Per-row scalar outputs: 3 values, written by block 0 of each row.
    if (blockIdx.x == 0 && threadIdx.x < 3) {
        const float theta   = acosf(t);
        const float theta_m = acosf(ft);
        float v;
        if      (threadIdx.x == 0) v = sinf(theta);
        else if (threadIdx.x == 1) v = sinf(theta_m);
        else                       v = sinf(theta_m - theta);
        // layout: [ diff[B,C-1] | sin_theta[B] | sin_theta_plus_m[B] | sin_m[B] ]
        out[(size_t)B * (size_t)(C - 1) + (size_t)threadIdx.x * B + b] = v;
    }

    const int start = blockIdx.x * CHUNK;
    const int end   = min(start + CHUNK, C);

    // Stride-coalesced scalar loop. Consecutive lanes touch consecutive
    // elements: fully coalesced on load; store shifted by at most one
    // element past the label column (<= 12.5% extra write sectors in the
    // one affected row segment). Unroll 8 for MLP (front-batched LDGs).
    #pragma unroll 8
    for (int c = start + threadIdx.x; c < end; c += TPB) {
        const float x = row[c];
        const float v = SCALE_S * (x - ft);
        if (c != lab) {
            const int oc = c - (c > lab);         // compact out the label col
            orow[oc] = v;
        }
    }
}

extern "C" void kernel_launch(void* const* d_in, const int* in_sizes, int n_in,
                              void* d_out, int out_size)
{
    const float* logits = (const float*)d_in[0];
    const int*   labels = (const int*)d_in[1];
    float*       out    = (float*)d_out;

    const int B = in_sizes[1];            // 512
    const int C = in_sizes[0] / B;        // 100000

    dim3 grid((C + CHUNK - 1) / CHUNK, B);
    cosface_kernel<<<grid, TPB>>>(logits, labels, out, B, C);
}

// round 6
// speedup vs baseline: 1.6828x; 1.6828x over previous
#include <cuda_runtime.h>
#include <cuda_bf16.h>

// CosFace margin transform.
// Inputs:  d_in[0] = logits  [B, C]  float32  (B=512, C=100000)
//          d_in[1] = labels  [B]     int32 OR int64 (detected in-kernel)
// Output:  d_out = concat( diff_logits[B, C-1], sin_theta[B], sin_theta_plus_m[B], sin_m[B] ) float32
//
// R5 post-mortem: scalar LDG.32 version was latency-bound (DRAM 39.9%, no
// pipe >40%, regs=32 capping MLP). R6: float4 loads -> 4x bytes-in-flight
// per instruction. Stores stay scalar (compaction shift breaks out
// alignment; stores have no result latency so they don't gate MLP).

static constexpr float SCALE_S  = 64.0f;
static constexpr float MARGIN_M = 0.35f;
static constexpr int   CHUNK    = 4096;   // columns per block (multiple of 4*TPB)
static constexpr int   TPB      = 256;    // threads per block

__global__ __launch_bounds__(TPB)
void cosface_kernel(const float* __restrict__ logits,
                    const int* __restrict__ labels32,  // raw label words
                    float* __restrict__ out,
                    int B, int C)
{
    // ---- Label-dtype detection (reads only B int32 words, safe for both
    // dtypes). int64 labels < C => all odd 32-bit words are 0. int32 =>
    // odd words are real labels; P(all zero) ~ (1e-5)^(B/2) ~ 0.
    __shared__ int s_nz;
    if (threadIdx.x == 0) s_nz = 0;
    __syncthreads();
    {
        int acc = 0;
        for (int i = threadIdx.x; i < B / 2; i += TPB)
            acc |= labels32[2 * i + 1];
        if (acc != 0) atomicOr(&s_nz, 1);
    }
    __syncthreads();
    const bool labels_are_i64 = (s_nz == 0);

    const int b = blockIdx.y;
    int lab = labels_are_i64 ? labels32[2 * b]     // low word of int64
                             : labels32[b];        // plain int32
    lab = min(max(lab, 0), C - 1);                 // hang-proof clamp

    const float* __restrict__ row = logits + (size_t)b * (size_t)C;
    const float t  = __ldg(row + lab);             // target logit (broadcast)
    const float ft = t - MARGIN_M;                 // final target logit

    float* __restrict__ orow = out + (size_t)b * (size_t)(C - 1);

    // Per-row scalar outputs: 3 values, written by block 0 of each row.
    if (blockIdx.x == 0 && threadIdx.x < 3) {
        const float theta   = acosf(t);
        const float theta_m = acosf(ft);
        float v;
        if      (threadIdx.x == 0) v = sinf(theta);
        else if (threadIdx.x == 1) v = sinf(theta_m);
        else                       v = sinf(theta_m - theta);
        // layout: [ diff[B,C-1] | sin_theta[B] | sin_theta_plus_m[B] | sin_m[B] ]
        out[(size_t)B * (size_t)(C - 1) + (size_t)threadIdx.x * B + b] = v;
    }

    const int start = blockIdx.x * CHUNK;
    const int end   = min(start + CHUNK, C);
    const int end4  = start + ((end - start) & ~3);   // float4-coverable extent

    // Vectorized main loop: LDG.128 per thread (512B/warp contiguous),
    // 4 scalar stores. CHUNK/(4*TPB) = 4 iterations, fully unrolled for MLP.
    #pragma unroll 4
    for (int c = start + threadIdx.x * 4; c < end4; c += TPB * 4) {
        const float4 x = *reinterpret_cast<const float4*>(row + c);
        float v0 = SCALE_S * (x.x - ft);
        float v1 = SCALE_S * (x.y - ft);
        float v2 = SCALE_S * (x.z - ft);
        float v3 = SCALE_S * (x.w - ft);
        // Uniform fast path: whole 4-wide group on one side of the label.
        if (c + 3 < lab) {
            orow[c + 0] = v0; orow[c + 1] = v1;
            orow[c + 2] = v2; orow[c + 3] = v3;
        } else if (c > lab) {
            orow[c - 1] = v0; orow[c + 0] = v1;
            orow[c + 1] = v2; orow[c + 2] = v3;
        } else {
            // Straddles the label column (at most one group per row).
            #pragma unroll
            for (int k = 0; k < 4; k++) {
                const int cc = c + k;
                const float v = (k == 0) ? v0 : (k == 1) ? v1 : (k == 2) ? v2 : v3;
                if (cc != lab) orow[cc - (cc > lab)] = v;
            }
        }
    }

    // Scalar tail (only if C % 4 != 0; absent for C=100000).
    for (int c = end4 + threadIdx.x; c < end; c += TPB) {
        const float v = SCALE_S * (row[c] - ft);
        if (c != lab) orow[c - (c > lab)] = v;
    }
}

extern "C" void kernel_launch(void* const* d_in, const int* in_sizes, int n_in,
                              void* d_out, int out_size)
{
    const float* logits = (const float*)d_in[0];
    const int*   labels = (const int*)d_in[1];
    float*       out    = (float*)d_out;

    const int B = in_sizes[1];            // 512
    const int C = in_sizes[0] / B;        // 100000

    dim3 grid((C + CHUNK - 1) / CHUNK, B);
    cosface_kernel<<<grid, TPB>>>(logits, labels, out, B, C);
}

// round 7
// speedup vs baseline: 1.7501x; 1.0400x over previous
#include <cuda_runtime.h>
#include <cuda_bf16.h>

// CosFace margin transform.
// Inputs:  d_in[0] = logits  [B, C]  float32  (B=512, C=100000)
//          d_in[1] = labels  [B]     int32 OR int64 (detected in-kernel)
// Output:  d_out = concat( diff_logits[B, C-1], sin_theta[B], sin_theta_plus_m[B], sin_m[B] ) float32
//
// R6 post-mortem: float4 loads got 68.5us @ DRAM 66.8% (5.29TB/s), traffic
// near-ideal (~362MB measured), MLP ample. R7: streaming cache hints
// (__ldcs/__stcs) so the one-touch 410MB stream doesn't churn L2, plus
// 2x float4 per thread per iteration (fewer loop/branch overheads, more
// front-batched LDG.128s).

static constexpr float SCALE_S  = 64.0f;
static constexpr float MARGIN_M = 0.35f;
static constexpr int   CHUNK    = 8192;   // columns per block (= 4 iters * 2 * 4 * TPB)
static constexpr int   TPB      = 256;    // threads per block

__device__ __forceinline__ void store_group4(float* __restrict__ orow,
                                             int c, int lab,
                                             float v0, float v1, float v2, float v3)
{
    // Uniform fast paths: whole 4-wide group strictly on one side of label.
    if (c + 3 < lab) {
        __stcs(orow + c + 0, v0); __stcs(orow + c + 1, v1);
        __stcs(orow + c + 2, v2); __stcs(orow + c + 3, v3);
    } else if (c > lab) {
        __stcs(orow + c - 1, v0); __stcs(orow + c + 0, v1);
        __stcs(orow + c + 1, v2); __stcs(orow + c + 2, v3);
    } else {
        // Straddles the label column (at most one group per row).
        if (c + 0 != lab) __stcs(orow + (c + 0) - (c + 0 > lab), v0);
        if (c + 1 != lab) __stcs(orow + (c + 1) - (c + 1 > lab), v1);
        if (c + 2 != lab) __stcs(orow + (c + 2) - (c + 2 > lab), v2);
        if (c + 3 != lab) __stcs(orow + (c + 3) - (c + 3 > lab), v3);
    }
}

__global__ __launch_bounds__(TPB)
void cosface_kernel(const float* __restrict__ logits,
                    const int* __restrict__ labels32,  // raw label words
                    float* __restrict__ out,
                    int B, int C)
{
    // ---- Label-dtype detection (reads only B int32 words, safe for both
    // dtypes). int64 labels < C => all odd 32-bit words are 0. int32 =>
    // odd words are real labels; P(all zero) ~ (1e-5)^(B/2) ~ 0.
    __shared__ int s_nz;
    if (threadIdx.x == 0) s_nz = 0;
    __syncthreads();
    {
        int acc = 0;
        for (int i = threadIdx.x; i < B / 2; i += TPB)
            acc |= labels32[2 * i + 1];
        if (acc != 0) atomicOr(&s_nz, 1);
    }
    __syncthreads();
    const bool labels_are_i64 = (s_nz == 0);

    const int b = blockIdx.y;
    int lab = labels_are_i64 ? labels32[2 * b]     // low word of int64
                             : labels32[b];        // plain int32
    lab = min(max(lab, 0), C - 1);                 // hang-proof clamp

    const float* __restrict__ row = logits + (size_t)b * (size_t)C;
    const float t  = __ldg(row + lab);             // target logit (broadcast, keep cached)
    const float ft = t - MARGIN_M;                 // final target logit

    float* __restrict__ orow = out + (size_t)b * (size_t)(C - 1);

    // Per-row scalar outputs: 3 values, written by block 0 of each row.
    if (blockIdx.x == 0 && threadIdx.x < 3) {
        const float theta   = acosf(t);
        const float theta_m = acosf(ft);
        float v;
        if      (threadIdx.x == 0) v = sinf(theta);
        else if (threadIdx.x == 1) v = sinf(theta_m);
        else                       v = sinf(theta_m - theta);
        // layout: [ diff[B,C-1] | sin_theta[B] | sin_theta_plus_m[B] | sin_m[B] ]
        out[(size_t)B * (size_t)(C - 1) + (size_t)threadIdx.x * B + b] = v;
    }

    const int start = blockIdx.x * CHUNK;
    const int end   = min(start + CHUNK, C);
    const int end4  = start + ((end - start) & ~3);   // float4-coverable extent

    // Main loop: 2 x LDG.128 per thread per iteration (streaming hint),
    // 8 scalar streaming stores. 4 iterations fully unrolled when the
    // block owns a full CHUNK.
    int c = start + threadIdx.x * 4;
    #pragma unroll 4
    for (; c + TPB * 4 + 3 < end4; c += TPB * 8) {
        const float4 xa = __ldcs(reinterpret_cast<const float4*>(row + c));
        const float4 xb = __ldcs(reinterpret_cast<const float4*>(row + c + TPB * 4));
        store_group4(orow, c, lab,
                     SCALE_S * (xa.x - ft), SCALE_S * (xa.y - ft),
                     SCALE_S * (xa.z - ft), SCALE_S * (xa.w - ft));
        store_group4(orow, c + TPB * 4, lab,
                     SCALE_S * (xb.x - ft), SCALE_S * (xb.y - ft),
                     SCALE_S * (xb.z - ft), SCALE_S * (xb.w - ft));
    }
    // Remainder vector groups (partial last chunk of each row).
    for (; c < end4; c += TPB * 4) {
        const float4 x = __ldcs(reinterpret_cast<const float4*>(row + c));
        store_group4(orow, c, lab,
                     SCALE_S * (x.x - ft), SCALE_S * (x.y - ft),
                     SCALE_S * (x.z - ft), SCALE_S * (x.w - ft));
    }

    // Scalar tail (only if C % 4 != 0; absent for C=100000).
    for (int cc = end4 + threadIdx.x; cc < end; cc += TPB) {
        const float v = SCALE_S * (__ldcs(row + cc) - ft);
        if (cc != lab) __stcs(orow + cc - (cc > lab), v);
    }
}

extern "C" void kernel_launch(void* const* d_in, const int* in_sizes, int n_in,
                              void* d_out, int out_size)
{
    const float* logits = (const float*)d_in[0];
    const int*   labels = (const int*)d_in[1];
    float*       out    = (float*)d_out;

    const int B = in_sizes[1];            // 512
    const int C = in_sizes[0] / B;        // 100000

    dim3 grid((C + CHUNK - 1) / CHUNK, B);
    cosface_kernel<<<grid, TPB>>>(logits, labels, out, B, C);
}